// round 13
// baseline (speedup 1.0000x reference)
#include <cuda_runtime.h>
#include <cstddef>

// ---------------------------------------------------------------------------
// Shapes (fixed): B=4, SQ=2048, SK=1024, D=1024
// R12 kernel (best: 1796us) + ONE change: A stored PRE-DUPLICATED in smem
// (dup'd u64 per element at STS time), so the inner loop reads FFMA2 'a'
// operands directly via LDS.128 — the 8 per-kk MOV dups vanish from both
// the issue stream and the LDS->FFMA2 dependency chain.
// ---------------------------------------------------------------------------
#define BB   4
#define SQ   2048
#define SK   1024
#define DD   1024

__device__ float g_k  [BB * SK * DD];
__device__ float g_v  [BB * SK * DD];
__device__ float g_qy [BB * SQ * DD];
__device__ float g_inv[BB * SQ * DD];
__device__ float g_qk [BB * SQ * SK];

typedef unsigned long long u64;

__device__ __forceinline__ u64 pack_dup(float a) {
    u64 r;
    asm("mov.b64 %0, {%1, %1};" : "=l"(r) : "f"(a));
    return r;
}
__device__ __forceinline__ void fma2(u64 &d, u64 a, u64 b) {
    asm("fma.rn.f32x2 %0, %1, %2, %0;" : "+l"(d) : "l"(a), "l"(b));
}

// B-row swizzle: insert a 4-float gap after every 32 floats (validated R11).
__device__ __forceinline__ int bswz(int f) { return f + 4 * (f >> 5); }
#define RSB 140
#define RSA 264   // A row stride in floats: 128 dup'd u64 = 256 + 8 pad

// ---------------------------------------------------------------------------
// Tiled GEMM: C[M,N] = A[M,K] * op(B)  (+ epilogue)
//   MODEB = 0 : B is [N,K] row-major (NT) — linears, qk
//   MODEB = 1 : B is [K,N] row-major (NN) — attn @ v
//   EPI: 0 = +bias[n] | 1 = /= aux | 2 = none
// Tiles: 128x128, k-slab 8, 256 threads, 8x8/thread via FFMA2.
// ---------------------------------------------------------------------------
template <int MODEB, int EPI>
__global__ __launch_bounds__(256, 2) void gemm128(
    const float* __restrict__ A, const float* __restrict__ B,
    const float* __restrict__ aux, float* __restrict__ C,
    int M, int N, int K,
    size_t sA, size_t sB, size_t sC, size_t sX)
{
    __shared__ float As[2][8][RSA];     // dup'd: As[.][k][2m],[2m+1] equal
    __shared__ float Bs[2][8][RSB];

    const int tid = threadIdx.x;
    const int tx = tid & 15;
    const int ty = tid >> 4;
    const int z  = blockIdx.z;

    A   += (size_t)z * sA;
    B   += (size_t)z * sB;
    C   += (size_t)z * sC;
    aux += (size_t)z * sX;

    const int rm = blockIdx.y * 128;
    const int cn = blockIdx.x * 128;

    // per-thread load coordinates (one float4 each for A and B per slab)
    const int lrow = tid >> 1;            // 0..127
    const int lks  = (tid & 1) * 4;       // 0 or 4
    const int brow = bswz(lrow);          // swizzled B column (MODEB==0)
    const int bkr  = tid >> 5;            // 0..7   (MODEB==1)
    const int bns  = (tid & 31) * 4;      // 0..124 (MODEB==1)
    const int bnsw = bswz(bns);

    const float* Ag = A + (size_t)(rm + lrow) * K + lks;
    const float* Bg = (MODEB == 0)
        ? B + (size_t)(cn + lrow) * K + lks
        : B + (size_t)bkr * N + cn + bns;

    u64 acc[8][4];
    #pragma unroll
    for (int i = 0; i < 8; i++)
        #pragma unroll
        for (int p = 0; p < 4; p++) acc[i][p] = 0ull;

    const int boff = tx * 8 + 4 * (tx >> 2);   // swizzled B fragment offset
    const int nsl = K >> 3;

    float4 ra = *(const float4*)Ag;
    float4 rb = *(const float4*)Bg;

    for (int s = 0; s < nsl; s++) {
        const int buf = s & 1;

        // ---- store staged slab (A dup'd) ----
        {
            float* ap = &As[buf][lks][2 * lrow];
            *(u64*)(ap + 0 * RSA) = pack_dup(ra.x);
            *(u64*)(ap + 1 * RSA) = pack_dup(ra.y);
            *(u64*)(ap + 2 * RSA) = pack_dup(ra.z);
            *(u64*)(ap + 3 * RSA) = pack_dup(ra.w);
            if (MODEB == 0) {
                float* bp = &Bs[buf][lks][brow];
                bp[0 * RSB] = rb.x;
                bp[1 * RSB] = rb.y;
                bp[2 * RSB] = rb.z;
                bp[3 * RSB] = rb.w;
            } else {
                *(float4*)&Bs[buf][bkr][bnsw] = rb;
            }
        }
        __syncthreads();

        // ---- prefetch next slab (drains under compute) ----
        if (s + 1 < nsl) {
            const int k1 = (s + 1) * 8;
            ra = *(const float4*)(Ag + k1);
            rb = (MODEB == 0) ? *(const float4*)(Bg + k1)
                              : *(const float4*)(Bg + (size_t)k1 * N);
        }

        // ---- compute 8 kk: 6 LDS.128 + 32 FFMA2, zero MOVs ----
        #pragma unroll
        for (int kk = 0; kk < 8; kk++) {
            const u64* a64 = (const u64*)&As[buf][kk][16 * ty];
            ulonglong2 a01 = *(const ulonglong2*)(a64);
            ulonglong2 a23 = *(const ulonglong2*)(a64 + 2);
            ulonglong2 a45 = *(const ulonglong2*)(a64 + 4);
            ulonglong2 a67 = *(const ulonglong2*)(a64 + 6);
            u64 ad[8] = { a01.x, a01.y, a23.x, a23.y,
                          a45.x, a45.y, a67.x, a67.y };
            u64 bv[4];
            const u64* b64 = (const u64*)&Bs[buf][kk][boff];
            bv[0] = b64[0]; bv[1] = b64[1]; bv[2] = b64[2]; bv[3] = b64[3];
            #pragma unroll
            for (int i = 0; i < 8; i++)
                #pragma unroll
                for (int p = 0; p < 4; p++) fma2(acc[i][p], ad[i], bv[p]);
        }
    }

    // ---- epilogue + store (unchanged) ----
    #pragma unroll
    for (int i = 0; i < 8; i++) {
        int r = rm + ty * 8 + i;
        size_t base = (size_t)r * N + cn + tx * 8;
        float c[8];
        #pragma unroll
        for (int p = 0; p < 4; p++) {
            float2 f2 = *(float2*)&acc[i][p];
            c[2 * p + 0] = f2.x;
            c[2 * p + 1] = f2.y;
        }
        if (EPI == 0) {
            #pragma unroll
            for (int j = 0; j < 8; j++) c[j] += aux[cn + tx * 8 + j];
        } else if (EPI == 1) {
            #pragma unroll
            for (int j = 0; j < 8; j++) c[j] /= aux[base + j];
        }
        *(float4*)(C + base)     = *(float4*)&c[0];
        *(float4*)(C + base + 4) = *(float4*)&c[4];
    }
}

// ---------------------------------------------------------------------------
// Row softmax over N=1024, one 256-thread block per row, in place.
// ---------------------------------------------------------------------------
__global__ __launch_bounds__(256) void softmax1024(float* __restrict__ data)
{
    float* p = data + (size_t)blockIdx.x * 1024;
    const int t    = threadIdx.x;
    const int lane = t & 31;
    const int warp = t >> 5;

    __shared__ float redbuf[8];
    __shared__ float stat[2];

    float4 x = *((const float4*)p + t);

    float m = fmaxf(fmaxf(x.x, x.y), fmaxf(x.z, x.w));
    #pragma unroll
    for (int o = 16; o > 0; o >>= 1)
        m = fmaxf(m, __shfl_xor_sync(0xffffffffu, m, o));
    if (lane == 0) redbuf[warp] = m;
    __syncthreads();
    if (t == 0) {
        float mm = redbuf[0];
        #pragma unroll
        for (int i = 1; i < 8; i++) mm = fmaxf(mm, redbuf[i]);
        stat[0] = mm;
    }
    __syncthreads();
    const float bm = stat[0];

    x.x = __expf(x.x - bm);
    x.y = __expf(x.y - bm);
    x.z = __expf(x.z - bm);
    x.w = __expf(x.w - bm);

    float s = (x.x + x.y) + (x.z + x.w);
    #pragma unroll
    for (int o = 16; o > 0; o >>= 1)
        s += __shfl_xor_sync(0xffffffffu, s, o);
    __syncthreads();
    if (lane == 0) redbuf[warp] = s;
    __syncthreads();
    if (t == 0) {
        float ss = redbuf[0];
        #pragma unroll
        for (int i = 1; i < 8; i++) ss += redbuf[i];
        stat[1] = 1.0f / ss;
    }
    __syncthreads();
    const float r = stat[1];

    x.x *= r; x.y *= r; x.z *= r; x.w *= r;
    *((float4*)p + t) = x;
}

// ---------------------------------------------------------------------------
// kernel_launch
// inputs: 0:x 1:y 2:W1 3:b1 4:W2 5:b2 6:W3 7:b3 8:W4 9:b4 10:W5 11:b5
// ---------------------------------------------------------------------------
extern "C" void kernel_launch(void* const* d_in, const int* in_sizes, int n_in,
                              void* d_out, int out_size)
{
    (void)in_sizes; (void)n_in; (void)out_size;

    const float* x  = (const float*)d_in[0];
    const float* y  = (const float*)d_in[1];
    const float* W2 = (const float*)d_in[4];
    const float* b2 = (const float*)d_in[5];
    const float* W3 = (const float*)d_in[6];
    const float* b3 = (const float*)d_in[7];
    const float* W4 = (const float*)d_in[8];
    const float* b4 = (const float*)d_in[9];
    const float* W5 = (const float*)d_in[10];
    const float* b5 = (const float*)d_in[11];
    float* out = (float*)d_out;

    void *pk, *pv, *pqy, *pinv, *pqk;
    cudaGetSymbolAddress(&pk,   g_k);
    cudaGetSymbolAddress(&pv,   g_v);
    cudaGetSymbolAddress(&pqy,  g_qy);
    cudaGetSymbolAddress(&pinv, g_inv);
    cudaGetSymbolAddress(&pqk,  g_qk);
    float* gk   = (float*)pk;
    float* gv   = (float*)pv;
    float* gqy  = (float*)pqy;
    float* ginv = (float*)pinv;
    float* gqk  = (float*)pqk;

    const dim3 blk(256);

    // linears (batch flattened into M)
    {
        dim3 grid_y(DD / 128, (BB * SK) / 128, 1);   // (8, 32)
        gemm128<0, 0><<<grid_y, blk>>>(y, W2, b2, gk, BB * SK, DD, DD, 0, 0, 0, 0);
        gemm128<0, 0><<<grid_y, blk>>>(y, W3, b3, gv, BB * SK, DD, DD, 0, 0, 0, 0);
        dim3 grid_x(DD / 128, (BB * SQ) / 128, 1);   // (8, 64)
        gemm128<0, 0><<<grid_x, blk>>>(x, W4, b4, gqy,  BB * SQ, DD, DD, 0, 0, 0, 0);
        gemm128<0, 0><<<grid_x, blk>>>(x, W5, b5, ginv, BB * SQ, DD, DD, 0, 0, 0, 0);
    }

    // qk = (qy @ k^T) / inv, per batch
    {
        dim3 grid(SK / 128, SQ / 128, BB);           // (8, 16, 4)
        gemm128<0, 1><<<grid, blk>>>(gqy, gk, ginv, gqk,
                                     SQ, SK, DD,
                                     (size_t)SQ * DD, (size_t)SK * DD,
                                     (size_t)SQ * SK, (size_t)SQ * DD);
    }

    // softmax rows (B*SQ rows of SK=1024)
    softmax1024<<<BB * SQ, blk>>>(gqk);

    // out = attn @ v, per batch
    {
        dim3 grid(DD / 128, SQ / 128, BB);           // (8, 16, 4)
        gemm128<1, 2><<<grid, blk>>>(gqk, gv, nullptr, out,
                                     SQ, DD, SK,
                                     (size_t)SQ * SK, (size_t)SK * DD,
                                     (size_t)SQ * DD, 0);
    }
}

// round 14
// speedup vs baseline: 1.4171x; 1.4171x over previous
#include <cuda_runtime.h>
#include <cstddef>

// ---------------------------------------------------------------------------
// Shapes (fixed): B=4, SQ=2048, SK=1024, D=1024
// R12 kernel (best: 1796us) + ONE change: the 4 independent linears are fused
// into a single 1536-CTA launch (identical tile geometry, pointer dispatch
// only) to remove wave-quantization tails. GEMM body untouched.
// ---------------------------------------------------------------------------
#define BB   4
#define SQ   2048
#define SK   1024
#define DD   1024

__device__ float g_k  [BB * SK * DD];
__device__ float g_v  [BB * SK * DD];
__device__ float g_qy [BB * SQ * DD];
__device__ float g_inv[BB * SQ * DD];
__device__ float g_qk [BB * SQ * SK];

typedef unsigned long long u64;

__device__ __forceinline__ u64 pack_dup(float a) {
    u64 r;
    asm("mov.b64 %0, {%1, %1};" : "=l"(r) : "f"(a));
    return r;
}
__device__ __forceinline__ void fma2(u64 &d, u64 a, u64 b) {
    asm("fma.rn.f32x2 %0, %1, %2, %0;" : "+l"(d) : "l"(a), "l"(b));
}

// B-row swizzle: insert a 4-float gap after every 32 floats (validated R11).
__device__ __forceinline__ int bswz(int f) { return f + 4 * (f >> 5); }
#define RSB 140

// ---------------------------------------------------------------------------
// GEMM tile body (VALIDATED R12 — do not modify):
// C[m0+128, n0+128] = A[M,K] * op(B) (+ epilogue)
//   MODEB = 0 : B is [N,K] row-major (NT) — linears, qk
//   MODEB = 1 : B is [K,N] row-major (NN) — attn @ v
//   EPI: 0 = +bias[n] | 1 = /= aux | 2 = none
// 128x128 tile, k-slab 8, double-buffered smem, reg prefetch, 1 barrier/slab.
// ---------------------------------------------------------------------------
template <int MODEB, int EPI>
__device__ __forceinline__ void run_gemm(
    const float* __restrict__ A, const float* __restrict__ B,
    const float* __restrict__ aux, float* __restrict__ C,
    int N, int K, int m0, int n0)
{
    __shared__ float As[2][8][132];
    __shared__ float Bs[2][8][RSB];

    const int tid = threadIdx.x;
    const int tx = tid & 15;
    const int ty = tid >> 4;

    // per-thread load coordinates (one float4 each for A and B per slab)
    const int lrow = tid >> 1;            // 0..127
    const int lks  = (tid & 1) * 4;       // 0 or 4
    const int brow = bswz(lrow);          // swizzled B column (MODEB==0)
    const int bkr  = tid >> 5;            // 0..7   (MODEB==1)
    const int bns  = (tid & 31) * 4;      // 0..124 (MODEB==1)
    const int bnsw = bswz(bns);

    const float* Ag = A + (size_t)(m0 + lrow) * K + lks;
    const float* Bg = (MODEB == 0)
        ? B + (size_t)(n0 + lrow) * K + lks
        : B + (size_t)bkr * N + n0 + bns;

    u64 acc[8][4];
    #pragma unroll
    for (int i = 0; i < 8; i++)
        #pragma unroll
        for (int p = 0; p < 4; p++) acc[i][p] = 0ull;

    const int boff = tx * 8 + 4 * (tx >> 2);   // swizzled B fragment offset
    const int nsl = K >> 3;

    float4 ra = *(const float4*)Ag;
    float4 rb = *(const float4*)Bg;

    for (int s = 0; s < nsl; s++) {
        const int buf = s & 1;

        // ---- store staged slab ----
        {
            float* ap = &As[buf][lks][lrow];
            ap[0 * 132] = ra.x;
            ap[1 * 132] = ra.y;
            ap[2 * 132] = ra.z;
            ap[3 * 132] = ra.w;
            if (MODEB == 0) {
                float* bp = &Bs[buf][lks][brow];
                bp[0 * RSB] = rb.x;
                bp[1 * RSB] = rb.y;
                bp[2 * RSB] = rb.z;
                bp[3 * RSB] = rb.w;
            } else {
                *(float4*)&Bs[buf][bkr][bnsw] = rb;
            }
        }
        __syncthreads();

        // ---- prefetch next slab (drains under compute) ----
        if (s + 1 < nsl) {
            const int k1 = (s + 1) * 8;
            ra = *(const float4*)(Ag + k1);
            rb = (MODEB == 0) ? *(const float4*)(Bg + k1)
                              : *(const float4*)(Bg + (size_t)k1 * N);
        }

        // ---- compute 8 kk ----
        #pragma unroll
        for (int kk = 0; kk < 8; kk++) {
            float a[8];
            *(float4*)&a[0] = *(const float4*)&As[buf][kk][ty * 8];
            *(float4*)&a[4] = *(const float4*)&As[buf][kk][ty * 8 + 4];
            u64 bv[4];
            const u64* b64 = (const u64*)&Bs[buf][kk][boff];
            bv[0] = b64[0]; bv[1] = b64[1]; bv[2] = b64[2]; bv[3] = b64[3];
            #pragma unroll
            for (int i = 0; i < 8; i++) {
                u64 ad = pack_dup(a[i]);
                #pragma unroll
                for (int p = 0; p < 4; p++) fma2(acc[i][p], ad, bv[p]);
            }
        }
    }

    // ---- epilogue + store ----
    #pragma unroll
    for (int i = 0; i < 8; i++) {
        int r = m0 + ty * 8 + i;
        size_t base = (size_t)r * N + n0 + tx * 8;
        float c[8];
        #pragma unroll
        for (int p = 0; p < 4; p++) {
            float2 f2 = *(float2*)&acc[i][p];
            c[2 * p + 0] = f2.x;
            c[2 * p + 1] = f2.y;
        }
        if (EPI == 0) {
            #pragma unroll
            for (int j = 0; j < 8; j++) c[j] += aux[n0 + tx * 8 + j];
        } else if (EPI == 1) {
            #pragma unroll
            for (int j = 0; j < 8; j++) c[j] /= aux[base + j];
        }
        *(float4*)(C + base)     = *(float4*)&c[0];
        *(float4*)(C + base + 4) = *(float4*)&c[4];
    }
}

// ---------------------------------------------------------------------------
// Fused linears: 1536 CTAs, pointer dispatch only (identical geometry).
//   [0,256)     k   = y @ W2^T + b2    (32 x 8 tiles)
//   [256,512)   v   = y @ W3^T + b3    (32 x 8 tiles)
//   [512,1024)  qy  = x @ W4^T + b4    (64 x 8 tiles)
//   [1024,1536) inv = x @ W5^T + b5    (64 x 8 tiles)
// ---------------------------------------------------------------------------
__global__ __launch_bounds__(256, 2) void k_lin4(
    const float* __restrict__ x, const float* __restrict__ y,
    const float* __restrict__ W2, const float* __restrict__ b2,
    const float* __restrict__ W3, const float* __restrict__ b3,
    const float* __restrict__ W4, const float* __restrict__ b4,
    const float* __restrict__ W5, const float* __restrict__ b5,
    float* __restrict__ gk, float* __restrict__ gv,
    float* __restrict__ gqy, float* __restrict__ ginv)
{
    const int t = blockIdx.x;
    const float *A, *B, *bias;
    float* C;
    int u, m0, n0;

    if (t < 256) {
        A = y; B = W2; bias = b2; C = gk;
        u = t;          m0 = (u >> 3) << 7; n0 = (u & 7) << 7;
    } else if (t < 512) {
        A = y; B = W3; bias = b3; C = gv;
        u = t - 256;    m0 = (u >> 3) << 7; n0 = (u & 7) << 7;
    } else if (t < 1024) {
        A = x; B = W4; bias = b4; C = gqy;
        u = t - 512;    m0 = (u >> 3) << 7; n0 = (u & 7) << 7;
    } else {
        A = x; B = W5; bias = b5; C = ginv;
        u = t - 1024;   m0 = (u >> 3) << 7; n0 = (u & 7) << 7;
    }
    run_gemm<0, 0>(A, B, bias, C, DD, DD, m0, n0);
}

// qk = (qy @ k^T) / inv, per batch z
__global__ __launch_bounds__(256, 2) void k_qk(
    const float* __restrict__ gqy, const float* __restrict__ gk,
    const float* __restrict__ ginv, float* __restrict__ gqk)
{
    const size_t z = blockIdx.z;
    run_gemm<0, 1>(gqy + z * ((size_t)SQ * DD),
                   gk  + z * ((size_t)SK * DD),
                   ginv + z * ((size_t)SQ * DD),
                   gqk + z * ((size_t)SQ * SK),
                   SK, DD, blockIdx.y * 128, blockIdx.x * 128);
}

// out = attn @ v, per batch z (v natural [s][d], MODEB=1)
__global__ __launch_bounds__(256, 2) void k_av(
    const float* __restrict__ gqk, const float* __restrict__ gv,
    float* __restrict__ out)
{
    const size_t z = blockIdx.z;
    run_gemm<1, 2>(gqk + z * ((size_t)SQ * SK),
                   gv  + z * ((size_t)SK * DD),
                   nullptr,
                   out + z * ((size_t)SQ * DD),
                   DD, SK, blockIdx.y * 128, blockIdx.x * 128);
}

// ---------------------------------------------------------------------------
// Row softmax over N=1024, one 256-thread block per row, in place.
// ---------------------------------------------------------------------------
__global__ __launch_bounds__(256) void softmax1024(float* __restrict__ data)
{
    float* p = data + (size_t)blockIdx.x * 1024;
    const int t    = threadIdx.x;
    const int lane = t & 31;
    const int warp = t >> 5;

    __shared__ float redbuf[8];
    __shared__ float stat[2];

    float4 x = *((const float4*)p + t);

    float m = fmaxf(fmaxf(x.x, x.y), fmaxf(x.z, x.w));
    #pragma unroll
    for (int o = 16; o > 0; o >>= 1)
        m = fmaxf(m, __shfl_xor_sync(0xffffffffu, m, o));
    if (lane == 0) redbuf[warp] = m;
    __syncthreads();
    if (t == 0) {
        float mm = redbuf[0];
        #pragma unroll
        for (int i = 1; i < 8; i++) mm = fmaxf(mm, redbuf[i]);
        stat[0] = mm;
    }
    __syncthreads();
    const float bm = stat[0];

    x.x = __expf(x.x - bm);
    x.y = __expf(x.y - bm);
    x.z = __expf(x.z - bm);
    x.w = __expf(x.w - bm);

    float s = (x.x + x.y) + (x.z + x.w);
    #pragma unroll
    for (int o = 16; o > 0; o >>= 1)
        s += __shfl_xor_sync(0xffffffffu, s, o);
    __syncthreads();
    if (lane == 0) redbuf[warp] = s;
    __syncthreads();
    if (t == 0) {
        float ss = redbuf[0];
        #pragma unroll
        for (int i = 1; i < 8; i++) ss += redbuf[i];
        stat[1] = 1.0f / ss;
    }
    __syncthreads();
    const float r = stat[1];

    x.x *= r; x.y *= r; x.z *= r; x.w *= r;
    *((float4*)p + t) = x;
}

// ---------------------------------------------------------------------------
// kernel_launch
// inputs: 0:x 1:y 2:W1 3:b1 4:W2 5:b2 6:W3 7:b3 8:W4 9:b4 10:W5 11:b5
// ---------------------------------------------------------------------------
extern "C" void kernel_launch(void* const* d_in, const int* in_sizes, int n_in,
                              void* d_out, int out_size)
{
    (void)in_sizes; (void)n_in; (void)out_size;

    const float* x  = (const float*)d_in[0];
    const float* y  = (const float*)d_in[1];
    const float* W2 = (const float*)d_in[4];
    const float* b2 = (const float*)d_in[5];
    const float* W3 = (const float*)d_in[6];
    const float* b3 = (const float*)d_in[7];
    const float* W4 = (const float*)d_in[8];
    const float* b4 = (const float*)d_in[9];
    const float* W5 = (const float*)d_in[10];
    const float* b5 = (const float*)d_in[11];
    float* out = (float*)d_out;

    void *pk, *pv, *pqy, *pinv, *pqk;
    cudaGetSymbolAddress(&pk,   g_k);
    cudaGetSymbolAddress(&pv,   g_v);
    cudaGetSymbolAddress(&pqy,  g_qy);
    cudaGetSymbolAddress(&pinv, g_inv);
    cudaGetSymbolAddress(&pqk,  g_qk);
    float* gk   = (float*)pk;
    float* gv   = (float*)pv;
    float* gqy  = (float*)pqy;
    float* ginv = (float*)pinv;
    float* gqk  = (float*)pqk;

    const dim3 blk(256);

    // 1) four independent linears, one 1536-CTA launch
    k_lin4<<<1536, blk>>>(x, y, W2, b2, W3, b3, W4, b4, W5, b5,
                          gk, gv, gqy, ginv);

    // 2) qk = (qy @ k^T) / inv, per batch
    k_qk<<<dim3(SK / 128, SQ / 128, BB), blk>>>(gqy, gk, ginv, gqk);

    // 3) softmax rows (B*SQ rows of SK=1024)
    softmax1024<<<BB * SQ, blk>>>(gqk);

    // 4) out = attn @ v, per batch
    k_av<<<dim3(DD / 128, SQ / 128, BB), blk>>>(gqk, gv, out);
}

// round 15
// speedup vs baseline: 1.4319x; 1.0104x over previous
#include <cuda_runtime.h>
#include <cstddef>

// ---------------------------------------------------------------------------
// Shapes (fixed): B=4, SQ=2048, SK=1024, D=1024
// R14 kernel (best: 1770us) + ONE change: k-slab 8 -> 16 (double-buffered,
// reg prefetch of 4 float4, ONE barrier per 16-k slab -> 64 barriers/tile,
// half of R14) with incremental pointer bumps. Inner per-kk loop untouched.
// ---------------------------------------------------------------------------
#define BB   4
#define SQ   2048
#define SK   1024
#define DD   1024

__device__ float g_k  [BB * SK * DD];
__device__ float g_v  [BB * SK * DD];
__device__ float g_qy [BB * SQ * DD];
__device__ float g_inv[BB * SQ * DD];
__device__ float g_qk [BB * SQ * SK];

typedef unsigned long long u64;

__device__ __forceinline__ u64 pack_dup(float a) {
    u64 r;
    asm("mov.b64 %0, {%1, %1};" : "=l"(r) : "f"(a));
    return r;
}
__device__ __forceinline__ void fma2(u64 &d, u64 a, u64 b) {
    asm("fma.rn.f32x2 %0, %1, %2, %0;" : "+l"(d) : "l"(a), "l"(b));
}

// B-row swizzle: insert a 4-float gap after every 32 floats (validated R11).
__device__ __forceinline__ int bswz(int f) { return f + 4 * (f >> 5); }
#define RSB 140

// ---------------------------------------------------------------------------
// GEMM tile body: C[m0+128, n0+128] = A * op(B) (+ epilogue)
//   MODEB = 0 : B is [N,K] row-major (NT) — linears, qk
//   MODEB = 1 : B is [K,N] row-major (NN) — attn @ v
//   EPI: 0 = +bias[n] | 1 = /= aux | 2 = none
// 128x128 tile, k-slab 16, double-buffered smem, reg prefetch, 1 barrier/slab.
// ---------------------------------------------------------------------------
template <int MODEB, int EPI>
__device__ __forceinline__ void run_gemm(
    const float* __restrict__ A, const float* __restrict__ B,
    const float* __restrict__ aux, float* __restrict__ C,
    int N, int K, int m0, int n0)
{
    __shared__ float As[2][16][132];
    __shared__ float Bs[2][16][RSB];

    const int tid = threadIdx.x;
    const int tx = tid & 15;
    const int ty = tid >> 4;

    // per-thread load coordinates (two float4 each for A and B per slab)
    const int lrow = tid >> 1;            // 0..127
    const int lks  = (tid & 1) * 4;       // 0 or 4   (also +8 for second half)
    const int brow = bswz(lrow);          // swizzled B column (MODEB==0)
    const int bkr  = tid >> 5;            // 0..7     (MODEB==1; also +8)
    const int bns  = (tid & 31) * 4;      // 0..124   (MODEB==1)
    const int bnsw = bswz(bns);

    const float* Ag = A + (size_t)(m0 + lrow) * K + lks;
    const float* Bg = (MODEB == 0)
        ? B + (size_t)(n0 + lrow) * K + lks
        : B + (size_t)bkr * N + n0 + bns;

    u64 acc[8][4];
    #pragma unroll
    for (int i = 0; i < 8; i++)
        #pragma unroll
        for (int p = 0; p < 4; p++) acc[i][p] = 0ull;

    const int boff = tx * 8 + 4 * (tx >> 2);   // swizzled B fragment offset
    const int nsl = K >> 4;                    // 16-k slabs

    float4 ra0 = *(const float4*)(Ag);
    float4 ra1 = *(const float4*)(Ag + 8);
    float4 rb0, rb1;
    if (MODEB == 0) {
        rb0 = *(const float4*)(Bg);
        rb1 = *(const float4*)(Bg + 8);
    } else {
        rb0 = *(const float4*)(Bg);
        rb1 = *(const float4*)(Bg + (size_t)8 * N);
    }
    Ag += 16;
    Bg += (MODEB == 0) ? 16 : (size_t)16 * N;

    for (int s = 0; s < nsl; s++) {
        const int buf = s & 1;

        // ---- store staged slab ----
        {
            float* ap = &As[buf][lks][lrow];
            ap[0 * 132] = ra0.x;
            ap[1 * 132] = ra0.y;
            ap[2 * 132] = ra0.z;
            ap[3 * 132] = ra0.w;
            ap[8 * 132] = ra1.x;
            ap[9 * 132] = ra1.y;
            ap[10 * 132] = ra1.z;
            ap[11 * 132] = ra1.w;
            if (MODEB == 0) {
                float* bp = &Bs[buf][lks][brow];
                bp[0 * RSB] = rb0.x;
                bp[1 * RSB] = rb0.y;
                bp[2 * RSB] = rb0.z;
                bp[3 * RSB] = rb0.w;
                bp[8 * RSB] = rb1.x;
                bp[9 * RSB] = rb1.y;
                bp[10 * RSB] = rb1.z;
                bp[11 * RSB] = rb1.w;
            } else {
                *(float4*)&Bs[buf][bkr][bnsw]     = rb0;
                *(float4*)&Bs[buf][bkr + 8][bnsw] = rb1;
            }
        }
        __syncthreads();

        // ---- prefetch next slab (drains under compute) ----
        if (s + 1 < nsl) {
            ra0 = *(const float4*)(Ag);
            ra1 = *(const float4*)(Ag + 8);
            if (MODEB == 0) {
                rb0 = *(const float4*)(Bg);
                rb1 = *(const float4*)(Bg + 8);
            } else {
                rb0 = *(const float4*)(Bg);
                rb1 = *(const float4*)(Bg + (size_t)8 * N);
            }
            Ag += 16;
            Bg += (MODEB == 0) ? 16 : (size_t)16 * N;
        }

        // ---- compute 16 kk (per-kk body identical to R12/R14) ----
        #pragma unroll
        for (int kk = 0; kk < 16; kk++) {
            float a[8];
            *(float4*)&a[0] = *(const float4*)&As[buf][kk][ty * 8];
            *(float4*)&a[4] = *(const float4*)&As[buf][kk][ty * 8 + 4];
            u64 bv[4];
            const u64* b64 = (const u64*)&Bs[buf][kk][boff];
            bv[0] = b64[0]; bv[1] = b64[1]; bv[2] = b64[2]; bv[3] = b64[3];
            #pragma unroll
            for (int i = 0; i < 8; i++) {
                u64 ad = pack_dup(a[i]);
                #pragma unroll
                for (int p = 0; p < 4; p++) fma2(acc[i][p], ad, bv[p]);
            }
        }
    }

    // ---- epilogue + store (unchanged) ----
    #pragma unroll
    for (int i = 0; i < 8; i++) {
        int r = m0 + ty * 8 + i;
        size_t base = (size_t)r * N + n0 + tx * 8;
        float c[8];
        #pragma unroll
        for (int p = 0; p < 4; p++) {
            float2 f2 = *(float2*)&acc[i][p];
            c[2 * p + 0] = f2.x;
            c[2 * p + 1] = f2.y;
        }
        if (EPI == 0) {
            #pragma unroll
            for (int j = 0; j < 8; j++) c[j] += aux[n0 + tx * 8 + j];
        } else if (EPI == 1) {
            #pragma unroll
            for (int j = 0; j < 8; j++) c[j] /= aux[base + j];
        }
        *(float4*)(C + base)     = *(float4*)&c[0];
        *(float4*)(C + base + 4) = *(float4*)&c[4];
    }
}

// ---------------------------------------------------------------------------
// Fused linears: 1536 CTAs, pointer dispatch only (identical geometry).
// ---------------------------------------------------------------------------
__global__ __launch_bounds__(256, 2) void k_lin4(
    const float* __restrict__ x, const float* __restrict__ y,
    const float* __restrict__ W2, const float* __restrict__ b2,
    const float* __restrict__ W3, const float* __restrict__ b3,
    const float* __restrict__ W4, const float* __restrict__ b4,
    const float* __restrict__ W5, const float* __restrict__ b5,
    float* __restrict__ gk, float* __restrict__ gv,
    float* __restrict__ gqy, float* __restrict__ ginv)
{
    const int t = blockIdx.x;
    const float *A, *B, *bias;
    float* C;
    int u, m0, n0;

    if (t < 256) {
        A = y; B = W2; bias = b2; C = gk;
        u = t;          m0 = (u >> 3) << 7; n0 = (u & 7) << 7;
    } else if (t < 512) {
        A = y; B = W3; bias = b3; C = gv;
        u = t - 256;    m0 = (u >> 3) << 7; n0 = (u & 7) << 7;
    } else if (t < 1024) {
        A = x; B = W4; bias = b4; C = gqy;
        u = t - 512;    m0 = (u >> 3) << 7; n0 = (u & 7) << 7;
    } else {
        A = x; B = W5; bias = b5; C = ginv;
        u = t - 1024;   m0 = (u >> 3) << 7; n0 = (u & 7) << 7;
    }
    run_gemm<0, 0>(A, B, bias, C, DD, DD, m0, n0);
}

// qk = (qy @ k^T) / inv, per batch z
__global__ __launch_bounds__(256, 2) void k_qk(
    const float* __restrict__ gqy, const float* __restrict__ gk,
    const float* __restrict__ ginv, float* __restrict__ gqk)
{
    const size_t z = blockIdx.z;
    run_gemm<0, 1>(gqy + z * ((size_t)SQ * DD),
                   gk  + z * ((size_t)SK * DD),
                   ginv + z * ((size_t)SQ * DD),
                   gqk + z * ((size_t)SQ * SK),
                   SK, DD, blockIdx.y * 128, blockIdx.x * 128);
}

// out = attn @ v, per batch z (v natural [s][d], MODEB=1)
__global__ __launch_bounds__(256, 2) void k_av(
    const float* __restrict__ gqk, const float* __restrict__ gv,
    float* __restrict__ out)
{
    const size_t z = blockIdx.z;
    run_gemm<1, 2>(gqk + z * ((size_t)SQ * SK),
                   gv  + z * ((size_t)SK * DD),
                   nullptr,
                   out + z * ((size_t)SQ * DD),
                   DD, SK, blockIdx.y * 128, blockIdx.x * 128);
}

// ---------------------------------------------------------------------------
// Row softmax over N=1024, one 256-thread block per row, in place.
// ---------------------------------------------------------------------------
__global__ __launch_bounds__(256) void softmax1024(float* __restrict__ data)
{
    float* p = data + (size_t)blockIdx.x * 1024;
    const int t    = threadIdx.x;
    const int lane = t & 31;
    const int warp = t >> 5;

    __shared__ float redbuf[8];
    __shared__ float stat[2];

    float4 x = *((const float4*)p + t);

    float m = fmaxf(fmaxf(x.x, x.y), fmaxf(x.z, x.w));
    #pragma unroll
    for (int o = 16; o > 0; o >>= 1)
        m = fmaxf(m, __shfl_xor_sync(0xffffffffu, m, o));
    if (lane == 0) redbuf[warp] = m;
    __syncthreads();
    if (t == 0) {
        float mm = redbuf[0];
        #pragma unroll
        for (int i = 1; i < 8; i++) mm = fmaxf(mm, redbuf[i]);
        stat[0] = mm;
    }
    __syncthreads();
    const float bm = stat[0];

    x.x = __expf(x.x - bm);
    x.y = __expf(x.y - bm);
    x.z = __expf(x.z - bm);
    x.w = __expf(x.w - bm);

    float s = (x.x + x.y) + (x.z + x.w);
    #pragma unroll
    for (int o = 16; o > 0; o >>= 1)
        s += __shfl_xor_sync(0xffffffffu, s, o);
    __syncthreads();
    if (lane == 0) redbuf[warp] = s;
    __syncthreads();
    if (t == 0) {
        float ss = redbuf[0];
        #pragma unroll
        for (int i = 1; i < 8; i++) ss += redbuf[i];
        stat[1] = 1.0f / ss;
    }
    __syncthreads();
    const float r = stat[1];

    x.x *= r; x.y *= r; x.z *= r; x.w *= r;
    *((float4*)p + t) = x;
}

// ---------------------------------------------------------------------------
// kernel_launch
// inputs: 0:x 1:y 2:W1 3:b1 4:W2 5:b2 6:W3 7:b3 8:W4 9:b4 10:W5 11:b5
// ---------------------------------------------------------------------------
extern "C" void kernel_launch(void* const* d_in, const int* in_sizes, int n_in,
                              void* d_out, int out_size)
{
    (void)in_sizes; (void)n_in; (void)out_size;

    const float* x  = (const float*)d_in[0];
    const float* y  = (const float*)d_in[1];
    const float* W2 = (const float*)d_in[4];
    const float* b2 = (const float*)d_in[5];
    const float* W3 = (const float*)d_in[6];
    const float* b3 = (const float*)d_in[7];
    const float* W4 = (const float*)d_in[8];
    const float* b4 = (const float*)d_in[9];
    const float* W5 = (const float*)d_in[10];
    const float* b5 = (const float*)d_in[11];
    float* out = (float*)d_out;

    void *pk, *pv, *pqy, *pinv, *pqk;
    cudaGetSymbolAddress(&pk,   g_k);
    cudaGetSymbolAddress(&pv,   g_v);
    cudaGetSymbolAddress(&pqy,  g_qy);
    cudaGetSymbolAddress(&pinv, g_inv);
    cudaGetSymbolAddress(&pqk,  g_qk);
    float* gk   = (float*)pk;
    float* gv   = (float*)pv;
    float* gqy  = (float*)pqy;
    float* ginv = (float*)pinv;
    float* gqk  = (float*)pqk;

    const dim3 blk(256);

    // 1) four independent linears, one 1536-CTA launch
    k_lin4<<<1536, blk>>>(x, y, W2, b2, W3, b3, W4, b4, W5, b5,
                          gk, gv, gqy, ginv);

    // 2) qk = (qy @ k^T) / inv, per batch
    k_qk<<<dim3(SK / 128, SQ / 128, BB), blk>>>(gqy, gk, ginv, gqk);

    // 3) softmax rows (B*SQ rows of SK=1024)
    softmax1024<<<BB * SQ, blk>>>(gqk);

    // 4) out = attn @ v, per batch
    k_av<<<dim3(DD / 128, SQ / 128, BB), blk>>>(gqk, gv, out);
}

// round 16
// speedup vs baseline: 1.5057x; 1.0515x over previous
#include <cuda_runtime.h>
#include <cstddef>

// ---------------------------------------------------------------------------
// Shapes (fixed): B=4, SQ=2048, SK=1024, D=1024
// R15 kernel (best: 1752us) + ONE change: the compute loop processes kk in
// PAIRS — fragments for kk and kk+1 are loaded back-to-back into separate
// registers (independent LDS->FFMA2 chains), then both compute blocks run.
// Doubles per-warp ILP across the LDS latency. Everything else untouched.
// ---------------------------------------------------------------------------
#define BB   4
#define SQ   2048
#define SK   1024
#define DD   1024

__device__ float g_k  [BB * SK * DD];
__device__ float g_v  [BB * SK * DD];
__device__ float g_qy [BB * SQ * DD];
__device__ float g_inv[BB * SQ * DD];
__device__ float g_qk [BB * SQ * SK];

typedef unsigned long long u64;

__device__ __forceinline__ u64 pack_dup(float a) {
    u64 r;
    asm("mov.b64 %0, {%1, %1};" : "=l"(r) : "f"(a));
    return r;
}
__device__ __forceinline__ void fma2(u64 &d, u64 a, u64 b) {
    asm("fma.rn.f32x2 %0, %1, %2, %0;" : "+l"(d) : "l"(a), "l"(b));
}

// B-row swizzle: insert a 4-float gap after every 32 floats (validated R11).
__device__ __forceinline__ int bswz(int f) { return f + 4 * (f >> 5); }
#define RSB 140

// ---------------------------------------------------------------------------
// GEMM tile body: C[m0+128, n0+128] = A * op(B) (+ epilogue)
//   MODEB = 0 : B is [N,K] row-major (NT) — linears, qk
//   MODEB = 1 : B is [K,N] row-major (NN) — attn @ v
//   EPI: 0 = +bias[n] | 1 = /= aux | 2 = none
// 128x128 tile, k-slab 16, double-buffered smem, reg prefetch, 1 barrier/slab.
// ---------------------------------------------------------------------------
template <int MODEB, int EPI>
__device__ __forceinline__ void run_gemm(
    const float* __restrict__ A, const float* __restrict__ B,
    const float* __restrict__ aux, float* __restrict__ C,
    int N, int K, int m0, int n0)
{
    __shared__ float As[2][16][132];
    __shared__ float Bs[2][16][RSB];

    const int tid = threadIdx.x;
    const int tx = tid & 15;
    const int ty = tid >> 4;

    const int lrow = tid >> 1;            // 0..127
    const int lks  = (tid & 1) * 4;       // 0 or 4   (also +8 for second half)
    const int brow = bswz(lrow);          // swizzled B column (MODEB==0)
    const int bkr  = tid >> 5;            // 0..7     (MODEB==1; also +8)
    const int bns  = (tid & 31) * 4;      // 0..124   (MODEB==1)
    const int bnsw = bswz(bns);

    const float* Ag = A + (size_t)(m0 + lrow) * K + lks;
    const float* Bg = (MODEB == 0)
        ? B + (size_t)(n0 + lrow) * K + lks
        : B + (size_t)bkr * N + n0 + bns;

    u64 acc[8][4];
    #pragma unroll
    for (int i = 0; i < 8; i++)
        #pragma unroll
        for (int p = 0; p < 4; p++) acc[i][p] = 0ull;

    const int boff = tx * 8 + 4 * (tx >> 2);   // swizzled B fragment offset
    const int nsl = K >> 4;                    // 16-k slabs

    float4 ra0 = *(const float4*)(Ag);
    float4 ra1 = *(const float4*)(Ag + 8);
    float4 rb0, rb1;
    if (MODEB == 0) {
        rb0 = *(const float4*)(Bg);
        rb1 = *(const float4*)(Bg + 8);
    } else {
        rb0 = *(const float4*)(Bg);
        rb1 = *(const float4*)(Bg + (size_t)8 * N);
    }
    Ag += 16;
    Bg += (MODEB == 0) ? 16 : (size_t)16 * N;

    for (int s = 0; s < nsl; s++) {
        const int buf = s & 1;

        // ---- store staged slab ----
        {
            float* ap = &As[buf][lks][lrow];
            ap[0 * 132] = ra0.x;
            ap[1 * 132] = ra0.y;
            ap[2 * 132] = ra0.z;
            ap[3 * 132] = ra0.w;
            ap[8 * 132] = ra1.x;
            ap[9 * 132] = ra1.y;
            ap[10 * 132] = ra1.z;
            ap[11 * 132] = ra1.w;
            if (MODEB == 0) {
                float* bp = &Bs[buf][lks][brow];
                bp[0 * RSB] = rb0.x;
                bp[1 * RSB] = rb0.y;
                bp[2 * RSB] = rb0.z;
                bp[3 * RSB] = rb0.w;
                bp[8 * RSB] = rb1.x;
                bp[9 * RSB] = rb1.y;
                bp[10 * RSB] = rb1.z;
                bp[11 * RSB] = rb1.w;
            } else {
                *(float4*)&Bs[buf][bkr][bnsw]     = rb0;
                *(float4*)&Bs[buf][bkr + 8][bnsw] = rb1;
            }
        }
        __syncthreads();

        // ---- prefetch next slab (drains under compute) ----
        if (s + 1 < nsl) {
            ra0 = *(const float4*)(Ag);
            ra1 = *(const float4*)(Ag + 8);
            if (MODEB == 0) {
                rb0 = *(const float4*)(Bg);
                rb1 = *(const float4*)(Bg + 8);
            } else {
                rb0 = *(const float4*)(Bg);
                rb1 = *(const float4*)(Bg + (size_t)8 * N);
            }
            Ag += 16;
            Bg += (MODEB == 0) ? 16 : (size_t)16 * N;
        }

        // ---- compute 16 kk in PAIRS: two independent LDS->FFMA2 chains ----
        #pragma unroll
        for (int kk = 0; kk < 16; kk += 2) {
            float a0[8], a1[8];
            u64 bv0[4], bv1[4];
            // both fragment loads issued back-to-back (independent)
            *(float4*)&a0[0] = *(const float4*)&As[buf][kk][ty * 8];
            *(float4*)&a0[4] = *(const float4*)&As[buf][kk][ty * 8 + 4];
            *(float4*)&a1[0] = *(const float4*)&As[buf][kk + 1][ty * 8];
            *(float4*)&a1[4] = *(const float4*)&As[buf][kk + 1][ty * 8 + 4];
            const u64* b0 = (const u64*)&Bs[buf][kk][boff];
            const u64* b1 = (const u64*)&Bs[buf][kk + 1][boff];
            bv0[0] = b0[0]; bv0[1] = b0[1]; bv0[2] = b0[2]; bv0[3] = b0[3];
            bv1[0] = b1[0]; bv1[1] = b1[1]; bv1[2] = b1[2]; bv1[3] = b1[3];
            #pragma unroll
            for (int i = 0; i < 8; i++) {
                u64 ad = pack_dup(a0[i]);
                #pragma unroll
                for (int p = 0; p < 4; p++) fma2(acc[i][p], ad, bv0[p]);
            }
            #pragma unroll
            for (int i = 0; i < 8; i++) {
                u64 ad = pack_dup(a1[i]);
                #pragma unroll
                for (int p = 0; p < 4; p++) fma2(acc[i][p], ad, bv1[p]);
            }
        }
    }

    // ---- epilogue + store (unchanged) ----
    #pragma unroll
    for (int i = 0; i < 8; i++) {
        int r = m0 + ty * 8 + i;
        size_t base = (size_t)r * N + n0 + tx * 8;
        float c[8];
        #pragma unroll
        for (int p = 0; p < 4; p++) {
            float2 f2 = *(float2*)&acc[i][p];
            c[2 * p + 0] = f2.x;
            c[2 * p + 1] = f2.y;
        }
        if (EPI == 0) {
            #pragma unroll
            for (int j = 0; j < 8; j++) c[j] += aux[n0 + tx * 8 + j];
        } else if (EPI == 1) {
            #pragma unroll
            for (int j = 0; j < 8; j++) c[j] /= aux[base + j];
        }
        *(float4*)(C + base)     = *(float4*)&c[0];
        *(float4*)(C + base + 4) = *(float4*)&c[4];
    }
}

// ---------------------------------------------------------------------------
// Fused linears: 1536 CTAs, pointer dispatch only (identical geometry).
// ---------------------------------------------------------------------------
__global__ __launch_bounds__(256, 2) void k_lin4(
    const float* __restrict__ x, const float* __restrict__ y,
    const float* __restrict__ W2, const float* __restrict__ b2,
    const float* __restrict__ W3, const float* __restrict__ b3,
    const float* __restrict__ W4, const float* __restrict__ b4,
    const float* __restrict__ W5, const float* __restrict__ b5,
    float* __restrict__ gk, float* __restrict__ gv,
    float* __restrict__ gqy, float* __restrict__ ginv)
{
    const int t = blockIdx.x;
    const float *A, *B, *bias;
    float* C;
    int u, m0, n0;

    if (t < 256) {
        A = y; B = W2; bias = b2; C = gk;
        u = t;          m0 = (u >> 3) << 7; n0 = (u & 7) << 7;
    } else if (t < 512) {
        A = y; B = W3; bias = b3; C = gv;
        u = t - 256;    m0 = (u >> 3) << 7; n0 = (u & 7) << 7;
    } else if (t < 1024) {
        A = x; B = W4; bias = b4; C = gqy;
        u = t - 512;    m0 = (u >> 3) << 7; n0 = (u & 7) << 7;
    } else {
        A = x; B = W5; bias = b5; C = ginv;
        u = t - 1024;   m0 = (u >> 3) << 7; n0 = (u & 7) << 7;
    }
    run_gemm<0, 0>(A, B, bias, C, DD, DD, m0, n0);
}

// qk = (qy @ k^T) / inv, per batch z
__global__ __launch_bounds__(256, 2) void k_qk(
    const float* __restrict__ gqy, const float* __restrict__ gk,
    const float* __restrict__ ginv, float* __restrict__ gqk)
{
    const size_t z = blockIdx.z;
    run_gemm<0, 1>(gqy + z * ((size_t)SQ * DD),
                   gk  + z * ((size_t)SK * DD),
                   ginv + z * ((size_t)SQ * DD),
                   gqk + z * ((size_t)SQ * SK),
                   SK, DD, blockIdx.y * 128, blockIdx.x * 128);
}

// out = attn @ v, per batch z (v natural [s][d], MODEB=1)
__global__ __launch_bounds__(256, 2) void k_av(
    const float* __restrict__ gqk, const float* __restrict__ gv,
    float* __restrict__ out)
{
    const size_t z = blockIdx.z;
    run_gemm<1, 2>(gqk + z * ((size_t)SQ * SK),
                   gv  + z * ((size_t)SK * DD),
                   nullptr,
                   out + z * ((size_t)SQ * DD),
                   DD, SK, blockIdx.y * 128, blockIdx.x * 128);
}

// ---------------------------------------------------------------------------
// Row softmax over N=1024, one 256-thread block per row, in place.
// ---------------------------------------------------------------------------
__global__ __launch_bounds__(256) void softmax1024(float* __restrict__ data)
{
    float* p = data + (size_t)blockIdx.x * 1024;
    const int t    = threadIdx.x;
    const int lane = t & 31;
    const int warp = t >> 5;

    __shared__ float redbuf[8];
    __shared__ float stat[2];

    float4 x = *((const float4*)p + t);

    float m = fmaxf(fmaxf(x.x, x.y), fmaxf(x.z, x.w));
    #pragma unroll
    for (int o = 16; o > 0; o >>= 1)
        m = fmaxf(m, __shfl_xor_sync(0xffffffffu, m, o));
    if (lane == 0) redbuf[warp] = m;
    __syncthreads();
    if (t == 0) {
        float mm = redbuf[0];
        #pragma unroll
        for (int i = 1; i < 8; i++) mm = fmaxf(mm, redbuf[i]);
        stat[0] = mm;
    }
    __syncthreads();
    const float bm = stat[0];

    x.x = __expf(x.x - bm);
    x.y = __expf(x.y - bm);
    x.z = __expf(x.z - bm);
    x.w = __expf(x.w - bm);

    float s = (x.x + x.y) + (x.z + x.w);
    #pragma unroll
    for (int o = 16; o > 0; o >>= 1)
        s += __shfl_xor_sync(0xffffffffu, s, o);
    __syncthreads();
    if (lane == 0) redbuf[warp] = s;
    __syncthreads();
    if (t == 0) {
        float ss = redbuf[0];
        #pragma unroll
        for (int i = 1; i < 8; i++) ss += redbuf[i];
        stat[1] = 1.0f / ss;
    }
    __syncthreads();
    const float r = stat[1];

    x.x *= r; x.y *= r; x.z *= r; x.w *= r;
    *((float4*)p + t) = x;
}

// ---------------------------------------------------------------------------
// kernel_launch
// inputs: 0:x 1:y 2:W1 3:b1 4:W2 5:b2 6:W3 7:b3 8:W4 9:b4 10:W5 11:b5
// ---------------------------------------------------------------------------
extern "C" void kernel_launch(void* const* d_in, const int* in_sizes, int n_in,
                              void* d_out, int out_size)
{
    (void)in_sizes; (void)n_in; (void)out_size;

    const float* x  = (const float*)d_in[0];
    const float* y  = (const float*)d_in[1];
    const float* W2 = (const float*)d_in[4];
    const float* b2 = (const float*)d_in[5];
    const float* W3 = (const float*)d_in[6];
    const float* b3 = (const float*)d_in[7];
    const float* W4 = (const float*)d_in[8];
    const float* b4 = (const float*)d_in[9];
    const float* W5 = (const float*)d_in[10];
    const float* b5 = (const float*)d_in[11];
    float* out = (float*)d_out;

    void *pk, *pv, *pqy, *pinv, *pqk;
    cudaGetSymbolAddress(&pk,   g_k);
    cudaGetSymbolAddress(&pv,   g_v);
    cudaGetSymbolAddress(&pqy,  g_qy);
    cudaGetSymbolAddress(&pinv, g_inv);
    cudaGetSymbolAddress(&pqk,  g_qk);
    float* gk   = (float*)pk;
    float* gv   = (float*)pv;
    float* gqy  = (float*)pqy;
    float* ginv = (float*)pinv;
    float* gqk  = (float*)pqk;

    const dim3 blk(256);

    // 1) four independent linears, one 1536-CTA launch
    k_lin4<<<1536, blk>>>(x, y, W2, b2, W3, b3, W4, b4, W5, b5,
                          gk, gv, gqy, ginv);

    // 2) qk = (qy @ k^T) / inv, per batch
    k_qk<<<dim3(SK / 128, SQ / 128, BB), blk>>>(gqy, gk, ginv, gqk);

    // 3) softmax rows (B*SQ rows of SK=1024)
    softmax1024<<<BB * SQ, blk>>>(gqk);

    // 4) out = attn @ v, per batch
    k_av<<<dim3(DD / 128, SQ / 128, BB), blk>>>(gqk, gv, out);
}